// round 1
// baseline (speedup 1.0000x reference)
#include <cuda_runtime.h>
#include <cstdint>

// Morton encode permutation for x of shape (B, C, 256, 256) fp32.
// out[plane][morton(i,j)] = x[plane][i][j], where morton interleaves
// bits: even bits <- j, odd bits <- i.
//
// Strategy: each thread owns 16 consecutive output (Morton) indices,
// which form a 4x4 spatial block of the input plane:
//   - 4x LDG.128 (4 rows, 4 contiguous floats each, 16B aligned)
//   - register shuffle into Morton order
//   - 4x STG.128 fully-coalesced consecutive stores
// Pure memory-bound permutation: 256 MiB traffic -> ~32us HBM floor.

static __device__ __forceinline__ unsigned compact_even_bits(unsigned v) {
    // Keep even-position bits of v and compact them into the low bits.
    v &= 0x55555555u;
    v = (v | (v >> 1)) & 0x33333333u;
    v = (v | (v >> 2)) & 0x0F0F0F0Fu;
    v = (v | (v >> 4)) & 0x00FF00FFu;
    v = (v | (v >> 8)) & 0x0000FFFFu;
    return v;
}

__global__ void __launch_bounds__(256)
morton_encode_kernel(const float* __restrict__ in,
                     float* __restrict__ out,
                     int nblk)  // number of 16-element Morton blocks
{
    int t = blockIdx.x * blockDim.x + threadIdx.x;
    if (t >= nblk) return;

    // 4096 blocks-of-16 per 256x256 plane.
    unsigned p  = (unsigned)t >> 12;        // plane index (b*C + c)
    unsigned bk = (unsigned)t & 4095u;      // block index within plane

    // Morton index m = bk*16 + off. Bits 4.. of m come from bk:
    //   even bits of bk -> j bits >=2, odd bits of bk -> i bits >=2.
    unsigned j = compact_even_bits(bk)      << 2;  // column of 4x4 block
    unsigned i = compact_even_bits(bk >> 1) << 2;  // row of 4x4 block

    size_t plane_base = (size_t)p << 16;    // 65536 floats per plane

    const float4* r =
        reinterpret_cast<const float4*>(in + plane_base + (size_t)i * 256u + j);
    // Rows are 256 floats = 64 float4 apart.
    float4 r0 = r[0];
    float4 r1 = r[64];
    float4 r2 = r[128];
    float4 r3 = r[192];

    // Within the 4x4 block, Morton offsets 0..15:
    //   bit0 = j0, bit1 = i0, bit2 = j1, bit3 = i1
    // off  0- 3: (i+0..1, j+0..1) -> {r0.x, r0.y, r1.x, r1.y}
    // off  4- 7: (i+0..1, j+2..3) -> {r0.z, r0.w, r1.z, r1.w}
    // off  8-11: (i+2..3, j+0..1) -> {r2.x, r2.y, r3.x, r3.y}
    // off 12-15: (i+2..3, j+2..3) -> {r2.z, r2.w, r3.z, r3.w}
    float4* o = reinterpret_cast<float4*>(out + plane_base) + ((size_t)bk << 2);
    o[0] = make_float4(r0.x, r0.y, r1.x, r1.y);
    o[1] = make_float4(r0.z, r0.w, r1.z, r1.w);
    o[2] = make_float4(r2.x, r2.y, r3.x, r3.y);
    o[3] = make_float4(r2.z, r2.w, r3.z, r3.w);
}

extern "C" void kernel_launch(void* const* d_in, const int* in_sizes, int n_in,
                              void* d_out, int out_size) {
    const float* in = (const float*)d_in[0];
    float* out = (float*)d_out;

    int nblk = out_size / 16;               // 16 floats per thread
    int threads = 256;
    int blocks = (nblk + threads - 1) / threads;
    morton_encode_kernel<<<blocks, threads>>>(in, out, nblk);
}

// round 2
// speedup vs baseline: 1.0045x; 1.0045x over previous
#include <cuda_runtime.h>
#include <cstdint>

// Morton encode permutation, x shape (B=8, C=64, 256, 256) fp32.
// out[plane][morton(i,j)] = x[plane][i][j].
//
// Strategy: smem-staged tiles so BOTH global streams are long sequential bursts.
//   tile = 32 rows x 256 cols (full width) = 32KB:
//     - input side: literally contiguous 32KB (full rows)
//     - output side: morton image = 4 contiguous 8KB chunks
//       (i bits 5..7 fixed => only m bits {0..10,12,14} vary)
//   Phase 1: coalesced LDG.128 -> STS.128 (row stride 260 floats, low-conflict)
//   Phase 2: per out-float4: 2x LDS.64 (2 cols x 2 rows) -> streaming STG.128

static __device__ __forceinline__ unsigned ceb(unsigned v) {
    // compact even-position bits into low bits
    v &= 0x55555555u;
    v = (v | (v >> 1)) & 0x33333333u;
    v = (v | (v >> 2)) & 0x0F0F0F0Fu;
    v = (v | (v >> 4)) & 0x00FF00FFu;
    v = (v | (v >> 8)) & 0x0000FFFFu;
    return v;
}

#define RS 260  // smem row stride in floats (260*4B = 65*16B: 16B-aligned, banks spread)

__global__ void __launch_bounds__(256)
morton_smem_kernel(const float4* __restrict__ in4, float4* __restrict__ out4)
{
    __shared__ float sm[32 * RS];   // 33280 B

    unsigned tid = threadIdx.x;
    unsigned b = blockIdx.x;
    unsigned plane = b >> 3;        // 8 tiles per 256x256 plane
    unsigned t = b & 7u;            // strip index: rows [t*32, t*32+32)

    // ---- Phase 1: contiguous 32KB read -> smem ----
    const float4* src = in4 + ((size_t)plane << 14) + ((size_t)t << 11);

    float4 r[8];
#pragma unroll
    for (int k = 0; k < 8; k++)
        r[k] = __ldcs(src + k * 256 + tid);     // fully coalesced, front-batched MLP=8

#pragma unroll
    for (int k = 0; k < 8; k++) {
        unsigned v = (unsigned)k * 256u + tid;
        unsigned row = v >> 6;                  // 64 float4 per row
        unsigned c4  = v & 63u;
        *reinterpret_cast<float4*>(&sm[row * RS + c4 * 4]) = r[k];
    }
    __syncthreads();

    // ---- Phase 2: morton-ordered write, 4 contiguous 8KB chunks ----
    // tile's morton base: i0 = t*32 contributes bits 11,13,15 of m (>>2 -> 9,11,13)
    unsigned tb = ((t & 1u) << 9) | (((t >> 1) & 1u) << 11) | (((t >> 2) & 1u) << 13);
    float4* dst = out4 + ((size_t)plane << 14) + tb;

#pragma unroll
    for (int k = 0; k < 8; k++) {
        unsigned w = (unsigned)k * 256u + tid;   // out float4 within tile [0,2048)
        unsigned chunk = w >> 9;                 // which 8KB chunk (j6,j7)
        unsigned tt = w & 511u;                  // dense position within chunk

        // tt bits: b0->j1 b1->i1 b2->j2 b3->i2 b4->j3 b5->i3 b6->j4 b7->i4 b8->j5
        unsigned j = (ceb(tt) << 1) | ((chunk & 1u) << 6) | ((chunk >> 1) << 7);
        unsigned i = ceb(tt >> 1) << 1;

        // out float4 = { (i,j), (i,j+1), (i+1,j), (i+1,j+1) }
        float2 lo = *reinterpret_cast<const float2*>(&sm[i * RS + j]);
        float2 hi = *reinterpret_cast<const float2*>(&sm[(i + 1) * RS + j]);

        unsigned oidx = ((chunk & 1u) << 10) | ((chunk >> 1) << 12) | tt;
        __stcs(dst + oidx, make_float4(lo.x, lo.y, hi.x, hi.y));
    }
}

extern "C" void kernel_launch(void* const* d_in, const int* in_sizes, int n_in,
                              void* d_out, int out_size) {
    const float4* in4 = (const float4*)d_in[0];
    float4* out4 = (float4*)d_out;

    int nblocks = out_size / 8192;   // 8192 floats (32x256 tile) per block
    morton_smem_kernel<<<nblocks, 256>>>(in4, out4);
}